// round 4
// baseline (speedup 1.0000x reference)
#include <cuda_runtime.h>

// ---------------------------------------------------------------------------
// SplitPool: segment-mean over ~4100 variable-size chunks of x (B*L rows, D=128),
// scattered into a zero-padded (B, max_n_peaks, D) output. Last chunk of each
// sample is dropped.
//
// Pipeline (all graph-capturable, allocation-free):
//   1. scan_kernel   : prefix-sum chunk_size -> g_chunk_start; pool starts.
//   2. zero_kernel   : zero g_sums partial-sum scratch.
//   3. pool_kernel   : balanced streaming reduction (512 rows per block),
//                      per-segment smem reduce + atomicAdd into g_sums.
//   4. write_kernel  : out[i,p,:] = p < n_peaks[i] ? g_sums[chunk]/count : 0.
// ---------------------------------------------------------------------------

#define DIM 128
#define DIM4 (DIM / 4)
#define MAX_CHUNKS 8192
#define MAX_B 64
#define ROWS_PER_BLOCK 512

__device__ int   g_chunk_start[MAX_CHUNKS + 1];  // row offset of each chunk
__device__ int   g_pool_start[MAX_B + 1];        // first chunk id of each sample
__device__ float g_sums[MAX_CHUNKS * DIM];       // per-chunk column sums

// ---------------------------------------------------------------------------
// Kernel 1: single-block scan. 1024 threads, each owns a contiguous slice.
// ---------------------------------------------------------------------------
__global__ void scan_kernel(const int* __restrict__ cs, int n_chunks,
                            const int* __restrict__ n_peaks, int B) {
    __shared__ int partial[1024];
    const int t = threadIdx.x;
    const int per = (n_chunks + 1023) >> 10;
    const int begin = t * per;
    const int end = min(begin + per, n_chunks);

    int s = 0;
    for (int i = begin; i < end; i++) s += cs[i];
    partial[t] = s;
    __syncthreads();

    // Hillis-Steele inclusive scan over 1024 thread sums
    #pragma unroll
    for (int off = 1; off < 1024; off <<= 1) {
        int v = (t >= off) ? partial[t - off] : 0;
        __syncthreads();
        partial[t] += v;
        __syncthreads();
    }

    int pref = (t == 0) ? 0 : partial[t - 1];
    for (int i = begin; i < end; i++) {
        g_chunk_start[i] = pref;
        pref += cs[i];
    }
    if (t == 1023) g_chunk_start[n_chunks] = partial[1023];

    if (t == 0) {
        int acc = 0;
        for (int i = 0; i < B; i++) {
            g_pool_start[i] = acc;
            acc += n_peaks[i] + 1;
        }
        g_pool_start[B] = acc;
    }
}

// ---------------------------------------------------------------------------
// Kernel 2: zero the partial-sum scratch (n_chunks * DIM floats).
// ---------------------------------------------------------------------------
__global__ void zero_kernel(int n4) {
    float4* p = reinterpret_cast<float4*>(g_sums);
    const float4 z = make_float4(0.f, 0.f, 0.f, 0.f);
    for (int i = blockIdx.x * blockDim.x + threadIdx.x; i < n4;
         i += gridDim.x * blockDim.x)
        p[i] = z;
}

// ---------------------------------------------------------------------------
// Kernel 3: balanced streaming reduction.
// Each block owns ROWS_PER_BLOCK rows. 256 threads: lane = column group
// (float4), warp = row offset within segment (stride 8, two accumulators
// per thread for MLP). Per chunk-segment: smem reduce across 8 warps, then
// one atomicAdd per column into g_sums[chunk].
// ---------------------------------------------------------------------------
__global__ __launch_bounds__(256) void pool_kernel(const float* __restrict__ x,
                                                   int n_chunks, int total_rows) {
    const int r0 = blockIdx.x * ROWS_PER_BLOCK;
    if (r0 >= total_rows) return;
    const int r_end = min(r0 + ROWS_PER_BLOCK, total_rows);

    const int lane = threadIdx.x & 31;
    const int w = threadIdx.x >> 5;  // 0..7

    __shared__ float s[8][DIM];

    // binary search: largest chunk c with g_chunk_start[c] <= r0
    int lo = 0, hi = n_chunks - 1;
    while (lo < hi) {
        int mid = (lo + hi + 1) >> 1;
        if (g_chunk_start[mid] <= r0) lo = mid; else hi = mid - 1;
    }
    int c = lo;

    const float4* __restrict__ xv = reinterpret_cast<const float4*>(x);
    int seg_start = r0;

    while (seg_start < r_end) {
        const int seg_end = min(g_chunk_start[c + 1], r_end);

        float4 a0 = make_float4(0.f, 0.f, 0.f, 0.f);
        float4 a1 = make_float4(0.f, 0.f, 0.f, 0.f);

        // warp w handles rows seg_start+w, +8, +16, ... ; unrolled x2 for MLP
        for (int r = seg_start + w; r < seg_end; r += 16) {
            float4 v = xv[(long long)r * DIM4 + lane];
            a0.x += v.x; a0.y += v.y; a0.z += v.z; a0.w += v.w;
            const int r2 = r + 8;
            if (r2 < seg_end) {
                float4 v2 = xv[(long long)r2 * DIM4 + lane];
                a1.x += v2.x; a1.y += v2.y; a1.z += v2.z; a1.w += v2.w;
            }
        }
        a0.x += a1.x; a0.y += a1.y; a0.z += a1.z; a0.w += a1.w;

        // cross-warp reduce in smem, then one atomicAdd per column
        *reinterpret_cast<float4*>(&s[w][lane * 4]) = a0;
        __syncthreads();
        if (threadIdx.x < DIM) {
            float sum = 0.f;
            #pragma unroll
            for (int i = 0; i < 8; i++) sum += s[i][threadIdx.x];
            atomicAdd(&g_sums[c * DIM + threadIdx.x], sum);
        }
        __syncthreads();

        seg_start = seg_end;
        c++;
    }
}

// ---------------------------------------------------------------------------
// Kernel 4: finalize. One warp per (sample, peak-slot). Gather means or zero.
// Writes EVERY output element (d_out is poisoned), so no separate zero pass.
// ---------------------------------------------------------------------------
__global__ __launch_bounds__(256) void write_kernel(float* __restrict__ out,
                                                    const int* __restrict__ cs,
                                                    const int* __restrict__ n_peaks,
                                                    int B, int P) {
    const int warp = (blockIdx.x * blockDim.x + threadIdx.x) >> 5;
    const int lane = threadIdx.x & 31;
    if (warp >= B * P) return;

    const int i = warp / P;
    const int p = warp - i * P;

    float4 v = make_float4(0.f, 0.f, 0.f, 0.f);
    if (p < n_peaks[i]) {
        const int c = g_pool_start[i] + p;
        const float inv = 1.0f / (float)max(cs[c], 1);
        float4 sum = *reinterpret_cast<const float4*>(&g_sums[c * DIM + lane * 4]);
        v = make_float4(sum.x * inv, sum.y * inv, sum.z * inv, sum.w * inv);
    }
    reinterpret_cast<float4*>(out)[(long long)warp * DIM4 + lane] = v;
}

// ---------------------------------------------------------------------------
// Launch
// ---------------------------------------------------------------------------
extern "C" void kernel_launch(void* const* d_in, const int* in_sizes, int n_in,
                              void* d_out, int out_size) {
    const float* x        = (const float*)d_in[0];
    const int*   cs       = (const int*)d_in[1];
    const int*   n_peaks  = (const int*)d_in[2];

    const int n_chunks   = in_sizes[1];
    const int B          = in_sizes[2];
    const int total_rows = in_sizes[0] / DIM;
    const int P          = out_size / (B * DIM);  // max_n_peaks

    // 1. scan (single block)
    scan_kernel<<<1, 1024>>>(cs, n_chunks, n_peaks, B);

    // 2. zero partial sums
    const int n4 = n_chunks * DIM / 4;
    zero_kernel<<<256, 256>>>(n4);

    // 3. balanced streaming reduction
    const int nblk = (total_rows + ROWS_PER_BLOCK - 1) / ROWS_PER_BLOCK;
    pool_kernel<<<nblk, 256>>>(x, n_chunks, total_rows);

    // 4. finalize: one warp per output slot
    const int n_slots = B * P;
    const int wblk = (n_slots * 32 + 255) / 256;
    write_kernel<<<wblk, 256>>>((float*)d_out, cs, n_peaks, B, P);
}

// round 5
// speedup vs baseline: 1.2937x; 1.2937x over previous
#include <cuda_runtime.h>

// ---------------------------------------------------------------------------
// SplitPool, round 4: 2-launch pipeline.
//   1. setup_kernel : block 0 -> shfl-scan chunk_size, per-chunk dest slot +
//                     1/count; blocks 1..N -> zero d_out.
//   2. pool_kernel  : warp-autonomous streaming reduction. One warp owns 64
//                     contiguous rows, 4 independent accumulators (MLP=4),
//                     pre-scaled atomicAdd straight into d_out. No smem,
//                     no __syncthreads, no intermediate buffers.
// ---------------------------------------------------------------------------

#define DIM 128
#define DIM4 (DIM / 4)
#define MAX_CHUNKS 8192
#define MAX_B 64
#define WARP_ROWS 64

__device__ int   g_chunk_start[MAX_CHUNKS + 1];  // row offset of each chunk
__device__ int   g_dest[MAX_CHUNKS];             // output float offset, -1 = dropped
__device__ float g_inv[MAX_CHUNKS];              // 1 / max(count, 1)

// ---------------------------------------------------------------------------
// Kernel 1: setup. Block 0: scan + chunk metadata. Blocks >=1: zero output.
// ---------------------------------------------------------------------------
__global__ __launch_bounds__(1024) void setup_kernel(
    const int* __restrict__ cs, int n_chunks,
    const int* __restrict__ np, int B, int P,
    float* __restrict__ out, int out_f4) {

    if (blockIdx.x > 0) {
        float4* o4 = reinterpret_cast<float4*>(out);
        const float4 z = make_float4(0.f, 0.f, 0.f, 0.f);
        for (int i = (blockIdx.x - 1) * blockDim.x + threadIdx.x; i < out_f4;
             i += (gridDim.x - 1) * blockDim.x)
            o4[i] = z;
        return;
    }

    __shared__ int warp_pref[32];
    __shared__ int s_pool[MAX_B + 1];
    __shared__ int s_np[MAX_B];

    const int t = threadIdx.x;
    const int lane = t & 31;
    const int w = t >> 5;
    const int per = (n_chunks + 1023) >> 10;   // <= 8 for MAX_CHUNKS=8192

    int v[8];
    int tot = 0;
    #pragma unroll
    for (int k = 0; k < 8; k++) {
        int idx = t * per + k;
        int val = (k < per && idx < n_chunks) ? cs[idx] : 0;
        v[k] = val;
        tot += val;
    }

    // inclusive warp scan of per-thread totals
    int inc = tot;
    #pragma unroll
    for (int off = 1; off < 32; off <<= 1) {
        int n = __shfl_up_sync(0xffffffffu, inc, off);
        if (lane >= off) inc += n;
    }
    if (lane == 31) warp_pref[w] = inc;
    if (t < B) s_np[t] = np[t];
    __syncthreads();

    if (w == 0) {
        int ws = warp_pref[lane];
        #pragma unroll
        for (int off = 1; off < 32; off <<= 1) {
            int n = __shfl_up_sync(0xffffffffu, ws, off);
            if (lane >= off) ws += n;
        }
        warp_pref[lane] = ws;   // inclusive scan of warp sums
    }
    __syncthreads();

    int pref = inc - tot + (w > 0 ? warp_pref[w - 1] : 0);  // exclusive prefix
    #pragma unroll
    for (int k = 0; k < 8; k++) {
        int idx = t * per + k;
        if (k < per && idx < n_chunks) {
            g_chunk_start[idx] = pref;
            pref += v[k];
        }
    }
    if (t == 1023) g_chunk_start[n_chunks] = warp_pref[31];

    if (t == 0) {
        int acc = 0;
        for (int i = 0; i < B; i++) { s_pool[i] = acc; acc += s_np[i] + 1; }
        s_pool[B] = acc;
    }
    __syncthreads();

    // per-chunk destination + inverse count
    #pragma unroll
    for (int k = 0; k < 8; k++) {
        int c = t * per + k;
        if (k >= per || c >= n_chunks) break;
        int i = 0;
        while (i < B - 1 && s_pool[i + 1] <= c) i++;
        int peak = c - s_pool[i];
        bool valid = peak < s_np[i];
        g_dest[c] = valid ? (i * P + peak) * DIM : -1;
        g_inv[c]  = 1.0f / (float)max(v[k], 1);
    }
}

// ---------------------------------------------------------------------------
// Kernel 2: warp-autonomous streaming reduction.
// One warp owns WARP_ROWS contiguous rows; lane = float4 column group.
// 4 independent accumulators for MLP; per segment, 4 pre-scaled atomicAdds
// per lane directly into the output. No smem, no block syncs.
// ---------------------------------------------------------------------------
__global__ __launch_bounds__(256) void pool_kernel(const float* __restrict__ x,
                                                   float* __restrict__ out,
                                                   int n_chunks, int total_rows) {
    const int gw = (blockIdx.x * blockDim.x + threadIdx.x) >> 5;
    const int lane = threadIdx.x & 31;
    const int r0 = gw * WARP_ROWS;
    if (r0 >= total_rows) return;
    const int r_end = min(r0 + WARP_ROWS, total_rows);

    // binary search: largest chunk c with g_chunk_start[c] <= r0
    int lo = 0, hi = n_chunks - 1;
    while (lo < hi) {
        int mid = (lo + hi + 1) >> 1;
        if (g_chunk_start[mid] <= r0) lo = mid; else hi = mid - 1;
    }
    int c = lo;

    const float4* __restrict__ xv = reinterpret_cast<const float4*>(x);
    int s = r0;

    while (s < r_end) {
        const int e = min(g_chunk_start[c + 1], r_end);

        float4 a0 = make_float4(0.f, 0.f, 0.f, 0.f);
        float4 a1 = a0, a2 = a0, a3 = a0;

        int r = s;
        for (; r + 4 <= e; r += 4) {
            float4 v0 = __ldcs(&xv[(long long)(r + 0) * DIM4 + lane]);
            float4 v1 = __ldcs(&xv[(long long)(r + 1) * DIM4 + lane]);
            float4 v2 = __ldcs(&xv[(long long)(r + 2) * DIM4 + lane]);
            float4 v3 = __ldcs(&xv[(long long)(r + 3) * DIM4 + lane]);
            a0.x += v0.x; a0.y += v0.y; a0.z += v0.z; a0.w += v0.w;
            a1.x += v1.x; a1.y += v1.y; a1.z += v1.z; a1.w += v1.w;
            a2.x += v2.x; a2.y += v2.y; a2.z += v2.z; a2.w += v2.w;
            a3.x += v3.x; a3.y += v3.y; a3.z += v3.z; a3.w += v3.w;
        }
        for (; r < e; r++) {
            float4 v0 = __ldcs(&xv[(long long)r * DIM4 + lane]);
            a0.x += v0.x; a0.y += v0.y; a0.z += v0.z; a0.w += v0.w;
        }

        a0.x += (a1.x + a2.x) + (a3.x);
        a0.y += (a1.y + a2.y) + (a3.y);
        a0.z += (a1.z + a2.z) + (a3.z);
        a0.w += (a1.w + a2.w) + (a3.w);

        const int dest = g_dest[c];
        if (dest >= 0) {
            const float inv = g_inv[c];
            float* o = out + dest + lane * 4;
            atomicAdd(o + 0, a0.x * inv);
            atomicAdd(o + 1, a0.y * inv);
            atomicAdd(o + 2, a0.z * inv);
            atomicAdd(o + 3, a0.w * inv);
        }

        s = e;
        c++;
    }
}

// ---------------------------------------------------------------------------
// Launch
// ---------------------------------------------------------------------------
extern "C" void kernel_launch(void* const* d_in, const int* in_sizes, int n_in,
                              void* d_out, int out_size) {
    const float* x       = (const float*)d_in[0];
    const int*   cs      = (const int*)d_in[1];
    const int*   n_peaks = (const int*)d_in[2];

    const int n_chunks   = in_sizes[1];
    const int B          = in_sizes[2];
    const int total_rows = in_sizes[0] / DIM;
    const int P          = out_size / (B * DIM);   // max_n_peaks

    // 1. setup: block 0 scans + builds chunk metadata; blocks 1..64 zero out.
    setup_kernel<<<65, 1024>>>(cs, n_chunks, n_peaks, B, P,
                               (float*)d_out, out_size / 4);

    // 2. pool: one warp per WARP_ROWS contiguous rows.
    const int n_warps = (total_rows + WARP_ROWS - 1) / WARP_ROWS;
    const int nblk = (n_warps * 32 + 255) / 256;
    pool_kernel<<<nblk, 256>>>(x, (float*)d_out, n_chunks, total_rows);
}